// round 1
// baseline (speedup 1.0000x reference)
#include <cuda_runtime.h>
#include <math.h>

#define Bsz 64
#define Tq  77
#define Dm  256
#define Hh  8
#define DFFm 2048
#define Mem 800

// ---------------- scratch (static device globals; no runtime allocation) ----------------
__device__ float g_qkv [Bsz*Tq*768];          // SA qkv projections
__device__ float g_attn[Bsz*Tq*Dm];           // attention output (reused SA/CA)
__device__ float g_proj[Bsz*Tq*Dm];           // out-proj / ffn2 output (reused)
__device__ float g_x1  [Bsz*Tq*Dm];           // after SA block
__device__ float g_x2  [Bsz*Tq*Dm];           // after CA block
__device__ float g_caq [Bsz*Tq*Dm];           // CA query proj
__device__ float g_cakv[Bsz*Mem*512];         // CA key/value proj (800 x 512 per batch)
__device__ float g_ffh [(size_t)Bsz*Tq*DFFm]; // FFN hidden

// ---------------- generic batched GEMM:  C[b] = A[b] @ W[sid[b]]^T + bias --------------
// Tile: BM=32, BN=64, BK=16, 256 threads, 2x4 per-thread microtile.
// A can be split across two source tensors at row `msplit` (for concat(im1,im2)).
template<bool RELU>
__global__ void gemm_bias(const float* __restrict__ A1, const float* __restrict__ A2,
                          int msplit, long a_bs,
                          const float* __restrict__ Wbank, long w_bs, int w_roff,
                          const float* __restrict__ Bbank, long b_bs,
                          const int* __restrict__ sid,
                          float* __restrict__ C, long c_bs,
                          int M, int Nn, int K)
{
    __shared__ float As[16][33];   // +1 pad: conflict-free transpose store
    __shared__ float Ws[16][68];   // +4 pad: 16B-aligned rows, cheap stores
    const int b   = blockIdx.z;
    const int s   = sid[b];
    const float* W  = Wbank + (long)s * w_bs + (long)w_roff * K;
    const float* Bi = Bbank + (long)s * b_bs + w_roff;
    const int m0 = blockIdx.y * 32;
    const int n0 = blockIdx.x * 64;
    const int tid = threadIdx.x;
    const int tx  = tid & 15;     // N dir (4 cols each)
    const int ty  = tid >> 4;     // M dir (2 rows each)

    float acc[2][4] = {};

    for (int k0 = 0; k0 < K; k0 += 16) {
        __syncthreads();
        // A tile: 32x16 = 512 elements
        #pragma unroll
        for (int r = 0; r < 2; r++) {
            int idx = tid + r * 256;
            int mm = idx >> 4, kk = idx & 15;
            int row = m0 + mm;
            float v = 0.f;
            if (row < M) {
                const float* Ap = (row < msplit)
                    ? (A1 + (long)b * a_bs + (long)row * K)
                    : (A2 + (long)b * a_bs + (long)(row - msplit) * K);
                v = Ap[k0 + kk];
            }
            As[kk][mm] = v;
        }
        // W tile: 64x16 = 1024 elements (Nn, K always multiples of 64/16 here)
        #pragma unroll
        for (int r = 0; r < 4; r++) {
            int idx = tid + r * 256;
            int nn = idx >> 4, kk = idx & 15;
            Ws[kk][nn] = W[(long)(n0 + nn) * K + k0 + kk];
        }
        __syncthreads();
        #pragma unroll
        for (int k = 0; k < 16; k++) {
            float a0 = As[k][ty * 2];
            float a1 = As[k][ty * 2 + 1];
            float4 w = *reinterpret_cast<const float4*>(&Ws[k][tx * 4]);
            acc[0][0] += a0 * w.x; acc[0][1] += a0 * w.y;
            acc[0][2] += a0 * w.z; acc[0][3] += a0 * w.w;
            acc[1][0] += a1 * w.x; acc[1][1] += a1 * w.y;
            acc[1][2] += a1 * w.z; acc[1][3] += a1 * w.w;
        }
    }

    float bias[4];
    #pragma unroll
    for (int u = 0; u < 4; u++) bias[u] = Bi[n0 + tx * 4 + u];
    #pragma unroll
    for (int r = 0; r < 2; r++) {
        int row = m0 + ty * 2 + r;
        if (row < M) {
            float* Cp = C + (long)b * c_bs + (long)row * Nn + n0 + tx * 4;
            #pragma unroll
            for (int u = 0; u < 4; u++) {
                float v = acc[r][u] + bias[u];
                if (RELU) v = fmaxf(v, 0.f);
                Cp[u] = v;
            }
        }
    }
}

// ---------------- attention: one thread per query row, online softmax ------------------
// grid = (H, B), block = 128 (77 active). K/V staged in smem chunks of 64 keys.
__global__ void attn_kernel(const float* __restrict__ Q,  int q_rs, long q_bs,
                            const float* __restrict__ Kp, int k_rs, long k_bs,
                            const float* __restrict__ Vp, int v_rs, long v_bs,
                            const unsigned char* __restrict__ m1, int m1_bs,
                            const unsigned char* __restrict__ m2, int m2_bs, int msplit,
                            int nk, float* __restrict__ O)
{
    __shared__ float ks[64][32];
    __shared__ float vs[64][32];
    __shared__ unsigned char mk[64];
    const int h = blockIdx.x, b = blockIdx.y;
    const int tid = threadIdx.x;
    const float* Qb = Q  + (long)b * q_bs + h * 32;
    const float* Kb = Kp + (long)b * k_bs + h * 32;
    const float* Vb = Vp + (long)b * v_bs + h * 32;

    float q[32], o[32];
    float m = -INFINITY, l = 0.f;
    const bool act = tid < Tq;
    if (act) {
        const float scl = 0.17677669529663687f;  // 1/sqrt(32)
        #pragma unroll
        for (int d = 0; d < 32; d++) { q[d] = Qb[(long)tid * q_rs + d] * scl; o[d] = 0.f; }
    }

    for (int j0 = 0; j0 < nk; j0 += 64) {
        int cnt = min(64, nk - j0);
        __syncthreads();
        for (int idx = tid; idx < cnt * 32; idx += 128) {
            int j = idx >> 5, d = idx & 31;
            ks[j][d] = Kb[(long)(j0 + j) * k_rs + d];
            vs[j][d] = Vb[(long)(j0 + j) * v_rs + d];
        }
        for (int j = tid; j < cnt; j += 128) {
            int jj = j0 + j;
            mk[j] = (jj < msplit) ? m1[(long)b * m1_bs + jj]
                                  : m2[(long)b * m2_bs + jj - msplit];
        }
        __syncthreads();
        if (act) {
            for (int j = 0; j < cnt; j++) {
                float s = 0.f;
                #pragma unroll
                for (int d = 0; d < 32; d++) s += q[d] * ks[j][d];
                if (mk[j]) s = -1e9f;
                if (s > m) {
                    float sc = __expf(m - s);   // expf(-inf)=0 handles first key
                    l = l * sc + 1.f;
                    #pragma unroll
                    for (int d = 0; d < 32; d++) o[d] = o[d] * sc + vs[j][d];
                    m = s;
                } else {
                    float p = __expf(s - m);
                    l += p;
                    #pragma unroll
                    for (int d = 0; d < 32; d++) o[d] += p * vs[j][d];
                }
            }
        }
    }
    if (act) {
        float inv = 1.f / l;
        float* Ob = O + ((long)b * Tq + tid) * Dm + h * 32;
        #pragma unroll
        for (int d = 0; d < 32; d++) Ob[d] = o[d] * inv;
    }
}

// ---------------- residual + layernorm: one block (256 thr) per row --------------------
__global__ void resid_ln(const float* __restrict__ X, const float* __restrict__ Y,
                         const float* __restrict__ Wb, const float* __restrict__ Bb,
                         const int* __restrict__ sid, float* __restrict__ Out)
{
    const int row = blockIdx.x;     // 0 .. B*T-1
    const int b = row / Tq;
    const int i = threadIdx.x;      // 0 .. 255
    const int s = sid[b];
    float v = X[(long)row * Dm + i] + Y[(long)row * Dm + i];

    float sum = v, sq = v * v;
    #pragma unroll
    for (int off = 16; off > 0; off >>= 1) {
        sum += __shfl_xor_sync(0xffffffffu, sum, off);
        sq  += __shfl_xor_sync(0xffffffffu, sq,  off);
    }
    __shared__ float sS[8], sQ[8];
    if ((i & 31) == 0) { sS[i >> 5] = sum; sQ[i >> 5] = sq; }
    __syncthreads();
    float ts = 0.f, tq = 0.f;
    #pragma unroll
    for (int k = 0; k < 8; k++) { ts += sS[k]; tq += sQ[k]; }

    float mean = ts * (1.f / 256.f);
    float var  = tq * (1.f / 256.f) - mean * mean;
    float rstd = rsqrtf(var + 1e-5f);
    Out[(long)row * Dm + i] = (v - mean) * rstd * Wb[(long)s * Dm + i] + Bb[(long)s * Dm + i];
}

// ---------------------------------- launch ---------------------------------------------
extern "C" void kernel_launch(void* const* d_in, const int* in_sizes, int n_in,
                              void* d_out, int out_size)
{
    const float*         text  = (const float*)d_in[0];
    const unsigned char* tmask = (const unsigned char*)d_in[1];
    const float*         im1   = (const float*)d_in[2];
    const unsigned char* imk1  = (const unsigned char*)d_in[3];
    const float*         im2   = (const float*)d_in[4];
    const unsigned char* imk2  = (const unsigned char*)d_in[5];
    const int*           sid   = (const int*)d_in[6];
    const float* sa_in_w  = (const float*)d_in[7];
    const float* sa_in_b  = (const float*)d_in[8];
    const float* sa_out_w = (const float*)d_in[9];
    const float* sa_out_b = (const float*)d_in[10];
    const float* ca_in_w  = (const float*)d_in[11];
    const float* ca_in_b  = (const float*)d_in[12];
    const float* ca_out_w = (const float*)d_in[13];
    const float* ca_out_b = (const float*)d_in[14];
    const float* l1w = (const float*)d_in[15];
    const float* l1b = (const float*)d_in[16];
    const float* l2w = (const float*)d_in[17];
    const float* l2b = (const float*)d_in[18];
    const float* n1w = (const float*)d_in[19];
    const float* n1b = (const float*)d_in[20];
    const float* n2w = (const float*)d_in[21];
    const float* n2b = (const float*)d_in[22];
    const float* n3w = (const float*)d_in[23];
    const float* n3b = (const float*)d_in[24];
    float* out = (float*)d_out;

    static float *qkv=nullptr,*attn=nullptr,*proj=nullptr,*x1=nullptr,*x2=nullptr,
                 *caq=nullptr,*cakv=nullptr,*ffh=nullptr;
    if (!qkv) {
        cudaGetSymbolAddress((void**)&qkv,  g_qkv);
        cudaGetSymbolAddress((void**)&attn, g_attn);
        cudaGetSymbolAddress((void**)&proj, g_proj);
        cudaGetSymbolAddress((void**)&x1,   g_x1);
        cudaGetSymbolAddress((void**)&x2,   g_x2);
        cudaGetSymbolAddress((void**)&caq,  g_caq);
        cudaGetSymbolAddress((void**)&cakv, g_cakv);
        cudaGetSymbolAddress((void**)&ffh,  g_ffh);
    }

    const int LNROWS = Bsz * Tq;

    // 1) SA qkv projection: (77,768) = text @ sa_in_w^T
    gemm_bias<false><<<dim3(768/64, (Tq+31)/32, Bsz), 256>>>(
        text, text, Tq, (long)Tq*Dm,
        sa_in_w, (long)768*Dm, 0, sa_in_b, 768, sid,
        qkv, (long)Tq*768, Tq, 768, Dm);

    // 2) SA attention
    attn_kernel<<<dim3(Hh, Bsz), 128>>>(
        qkv,       768, (long)Tq*768,
        qkv + 256, 768, (long)Tq*768,
        qkv + 512, 768, (long)Tq*768,
        tmask, Tq, tmask, 0, Tq + 1,
        Tq, attn);

    // 3) SA out proj
    gemm_bias<false><<<dim3(Dm/64, (Tq+31)/32, Bsz), 256>>>(
        attn, attn, Tq, (long)Tq*Dm,
        sa_out_w, (long)Dm*Dm, 0, sa_out_b, Dm, sid,
        proj, (long)Tq*Dm, Tq, Dm, Dm);

    // 4) residual + LN1 -> x1
    resid_ln<<<LNROWS, 256>>>(text, proj, n1w, n1b, sid, x1);

    // 5) CA query proj (rows [0:256) of ca_in_w)
    gemm_bias<false><<<dim3(Dm/64, (Tq+31)/32, Bsz), 256>>>(
        x1, x1, Tq, (long)Tq*Dm,
        ca_in_w, (long)768*Dm, 0, ca_in_b, 768, sid,
        caq, (long)Tq*Dm, Tq, Dm, Dm);

    // 6) CA key/value proj from concat(im1,im2), rows [256:768) of ca_in_w
    gemm_bias<false><<<dim3(512/64, Mem/32, Bsz), 256>>>(
        im1, im2, 400, (long)400*Dm,
        ca_in_w, (long)768*Dm, 256, ca_in_b, 768, sid,
        cakv, (long)Mem*512, Mem, 512, Dm);

    // 7) CA attention (nk=800, split masks at 400)
    attn_kernel<<<dim3(Hh, Bsz), 128>>>(
        caq,        Dm,  (long)Tq*Dm,
        cakv,       512, (long)Mem*512,
        cakv + 256, 512, (long)Mem*512,
        imk1, 400, imk2, 400, 400,
        Mem, attn);

    // 8) CA out proj
    gemm_bias<false><<<dim3(Dm/64, (Tq+31)/32, Bsz), 256>>>(
        attn, attn, Tq, (long)Tq*Dm,
        ca_out_w, (long)Dm*Dm, 0, ca_out_b, Dm, sid,
        proj, (long)Tq*Dm, Tq, Dm, Dm);

    // 9) residual + LN2 -> x2
    resid_ln<<<LNROWS, 256>>>(x1, proj, n2w, n2b, sid, x2);

    // 10) FFN up + relu
    gemm_bias<true><<<dim3(DFFm/64, (Tq+31)/32, Bsz), 256>>>(
        x2, x2, Tq, (long)Tq*Dm,
        l1w, (long)DFFm*Dm, 0, l1b, DFFm, sid,
        ffh, (long)Tq*DFFm, Tq, DFFm, Dm);

    // 11) FFN down
    gemm_bias<false><<<dim3(Dm/64, (Tq+31)/32, Bsz), 256>>>(
        ffh, ffh, Tq, (long)Tq*DFFm,
        l2w, (long)Dm*DFFm, 0, l2b, Dm, sid,
        proj, (long)Tq*Dm, Tq, Dm, DFFm);

    // 12) residual + LN3 -> output
    resid_ln<<<LNROWS, 256>>>(x2, proj, n3w, n3b, sid, out);
}

// round 3
// speedup vs baseline: 2.8573x; 2.8573x over previous
#include <cuda_runtime.h>
#include <math.h>
#include <cstdint>

#define Bsz 64
#define Tq  77
#define Dm  256
#define Hh  8
#define DFFm 2048
#define Mem 800

// ---------------- scratch (static device globals; no runtime allocation) ----------------
__device__ float g_qkv [Bsz*Tq*768];
__device__ float g_attn[Bsz*Tq*Dm];
__device__ float g_proj[Bsz*Tq*Dm];
__device__ float g_x1  [Bsz*Tq*Dm];
__device__ float g_x2  [Bsz*Tq*Dm];
__device__ float g_caq [Bsz*Tq*Dm];
__device__ float g_cakv[Bsz*Mem*512];
__device__ float g_ffh [(size_t)Bsz*Tq*DFFm];

__device__ __forceinline__ uint32_t smem_to_u32(const void* p) {
    uint32_t a;
    asm("{ .reg .u64 t; cvta.to.shared.u64 t, %1; cvt.u32.u64 %0, t; }" : "=r"(a) : "l"(p));
    return a;
}
__device__ __forceinline__ uint32_t f2tf32(float v) {
    uint32_t u;
    asm("cvt.rna.tf32.f32 %0, %1;" : "=r"(u) : "f"(v));
    return u;
}
__device__ __forceinline__ void mma_tf32(float* d, const uint32_t* a, const uint32_t* b) {
    asm volatile("mma.sync.aligned.m16n8k8.row.col.f32.tf32.tf32.f32 "
        "{%0,%1,%2,%3}, {%4,%5,%6,%7}, {%8,%9}, {%0,%1,%2,%3};"
        : "+f"(d[0]), "+f"(d[1]), "+f"(d[2]), "+f"(d[3])
        : "r"(a[0]), "r"(a[1]), "r"(a[2]), "r"(a[3]), "r"(b[0]), "r"(b[1]));
}
#define CP_ASYNC16(dst, src, sz) \
    asm volatile("cp.async.ca.shared.global [%0], [%1], 16, %2;" :: "r"(dst), "l"(src), "r"(sz))
#define CP_ASYNC16U(dst, src) \
    asm volatile("cp.async.ca.shared.global [%0], [%1], 16;" :: "r"(dst), "l"(src))
#define CP_COMMIT() asm volatile("cp.async.commit_group;" ::: "memory")

// ======== tf32 mma.sync GEMM: C[b] = A[b] @ W[sid[b]]^T + bias (+ReLU) ========
// CTA tile 64(M) x 128(N), BK=32. 8 warps as 2(M) x 4(N), each warp 32x32.
// Per warp-tile: 2 m-frags x 4 n-frags of m16n8k8. A split at row `msplit`.
#define PITCH 36
#define ASZ (64 * PITCH)            // floats
#define WSZ (128 * PITCH)
#define SMT ((ASZ + WSZ) * 2 * 4)   // 55296 bytes

template<bool RELU>
__global__ void __launch_bounds__(256) gemm_mma(
    const float* __restrict__ A1, const float* __restrict__ A2, int msplit, long a_bs,
    const float* __restrict__ Wbank, long w_bs, int w_roff,
    const float* __restrict__ Bbank, long b_bs, const int* __restrict__ sid,
    float* __restrict__ C, long c_bs, int M, int Nn, int K)
{
    extern __shared__ float smf[];
    float* As = smf;                    // [2][64][PITCH]
    float* Ws = smf + 2 * ASZ;          // [2][128][PITCH]
    const uint32_t sbA = smem_to_u32(As);
    const uint32_t sbW = smem_to_u32(Ws);

    const int tid  = threadIdx.x;
    const int wid  = tid >> 5;
    const int lane = tid & 31;
    const int b  = blockIdx.z;
    const int s  = sid[b];
    const int m0 = blockIdx.y * 64;
    const int n0 = blockIdx.x * 128;
    const float* W  = Wbank + (long)s * w_bs + (long)w_roff * K;
    const float* Bi = Bbank + (long)s * b_bs + w_roff;
    const int NC = K >> 5;

    const int wm = (wid >> 2) * 32;     // warp M offset in tile
    const int wn = (wid & 3) * 32;      // warp N offset in tile

    float acc[2][4][4];
    #pragma unroll
    for (int i = 0; i < 2; i++)
        #pragma unroll
        for (int j = 0; j < 4; j++)
            #pragma unroll
            for (int r = 0; r < 4; r++) acc[i][j][r] = 0.f;

    auto load_chunk = [&](int c, int p) {
        const int k0 = c << 5;
        // A: 64 rows x 8 float4 = 512, 2 per thread
        #pragma unroll
        for (int r = 0; r < 2; r++) {
            int idx = tid + (r << 8);
            int m = idx >> 3, c4 = idx & 7;
            int rg = m0 + m;
            const float* src = A1;
            uint32_t sz = 0;
            if (rg < M) {
                src = ((rg < msplit)
                    ? (A1 + (long)b * a_bs + (long)rg * K)
                    : (A2 + (long)b * a_bs + (long)(rg - msplit) * K)) + k0 + (c4 << 2);
                sz = 16;
            }
            CP_ASYNC16(sbA + (uint32_t)((p * ASZ + m * PITCH + (c4 << 2)) << 2), src, sz);
        }
        // W: 128 rows x 8 float4 = 1024, 4 per thread
        #pragma unroll
        for (int r = 0; r < 4; r++) {
            int idx = tid + (r << 8);
            int n = idx >> 3, c4 = idx & 7;
            const float* src = W + (long)(n0 + n) * K + k0 + (c4 << 2);
            CP_ASYNC16U(sbW + (uint32_t)((p * WSZ + n * PITCH + (c4 << 2)) << 2), src);
        }
        CP_COMMIT();
    };

    load_chunk(0, 0);

    const int lr = lane >> 2;   // 0..7
    const int lc = lane & 3;    // 0..3

    for (int c = 0; c < NC; c++) {
        const int p = c & 1;
        if (c + 1 < NC) {
            load_chunk(c + 1, (c + 1) & 1);
            asm volatile("cp.async.wait_group 1;" ::: "memory");
        } else {
            asm volatile("cp.async.wait_group 0;" ::: "memory");
        }
        __syncthreads();

        const float* Ab = As + p * ASZ;
        const float* Wb = Ws + p * WSZ;
        #pragma unroll
        for (int ks = 0; ks < 4; ks++) {
            const int k = ks << 3;
            uint32_t af[2][4], bf[4][2];
            #pragma unroll
            for (int mf = 0; mf < 2; mf++) {
                const float* ap = Ab + (wm + mf * 16 + lr) * PITCH + k + lc;
                af[mf][0] = f2tf32(ap[0]);
                af[mf][1] = f2tf32(ap[8 * PITCH]);
                af[mf][2] = f2tf32(ap[4]);
                af[mf][3] = f2tf32(ap[8 * PITCH + 4]);
            }
            #pragma unroll
            for (int nf = 0; nf < 4; nf++) {
                const float* wp = Wb + (wn + nf * 8 + lr) * PITCH + k + lc;
                bf[nf][0] = f2tf32(wp[0]);
                bf[nf][1] = f2tf32(wp[4]);
            }
            #pragma unroll
            for (int mf = 0; mf < 2; mf++)
                #pragma unroll
                for (int nf = 0; nf < 4; nf++)
                    mma_tf32(acc[mf][nf], af[mf], bf[nf]);
        }
        __syncthreads();
    }

    // ---- epilogue ----
    #pragma unroll
    for (int mf = 0; mf < 2; mf++) {
        const int row = m0 + wm + mf * 16 + lr;
        #pragma unroll
        for (int nf = 0; nf < 4; nf++) {
            const int col = n0 + wn + nf * 8 + 2 * lc;
            float b0 = Bi[col], b1 = Bi[col + 1];
            if (row < M) {
                float v0 = acc[mf][nf][0] + b0;
                float v1 = acc[mf][nf][1] + b1;
                if (RELU) { v0 = fmaxf(v0, 0.f); v1 = fmaxf(v1, 0.f); }
                *reinterpret_cast<float2*>(C + (long)b * c_bs + (long)row * Nn + col)
                    = make_float2(v0, v1);
            }
            if (row + 8 < M) {
                float v2 = acc[mf][nf][2] + b0;
                float v3 = acc[mf][nf][3] + b1;
                if (RELU) { v2 = fmaxf(v2, 0.f); v3 = fmaxf(v3, 0.f); }
                *reinterpret_cast<float2*>(C + (long)b * c_bs + (long)(row + 8) * Nn + col)
                    = make_float2(v2, v3);
            }
        }
    }
}

// ---------------- attention: one thread per query row, online softmax ------------------
__global__ void attn_kernel(const float* __restrict__ Q,  int q_rs, long q_bs,
                            const float* __restrict__ Kp, int k_rs, long k_bs,
                            const float* __restrict__ Vp, int v_rs, long v_bs,
                            const unsigned char* __restrict__ m1, int m1_bs,
                            const unsigned char* __restrict__ m2, int m2_bs, int msplit,
                            int nk, float* __restrict__ O)
{
    __shared__ float ks[64][32];
    __shared__ float vs[64][32];
    __shared__ unsigned char mk[64];
    const int h = blockIdx.x, b = blockIdx.y;
    const int tid = threadIdx.x;
    const float* Qb = Q  + (long)b * q_bs + h * 32;
    const float* Kb = Kp + (long)b * k_bs + h * 32;
    const float* Vb = Vp + (long)b * v_bs + h * 32;

    float q[32], o[32];
    float m = -INFINITY, l = 0.f;
    const bool act = tid < Tq;
    if (act) {
        const float scl = 0.17677669529663687f;
        #pragma unroll
        for (int d = 0; d < 32; d++) { q[d] = Qb[(long)tid * q_rs + d] * scl; o[d] = 0.f; }
    }

    for (int j0 = 0; j0 < nk; j0 += 64) {
        int cnt = min(64, nk - j0);
        __syncthreads();
        for (int idx = tid; idx < cnt * 32; idx += 128) {
            int j = idx >> 5, d = idx & 31;
            ks[j][d] = Kb[(long)(j0 + j) * k_rs + d];
            vs[j][d] = Vb[(long)(j0 + j) * v_rs + d];
        }
        for (int j = tid; j < cnt; j += 128) {
            int jj = j0 + j;
            mk[j] = (jj < msplit) ? m1[(long)b * m1_bs + jj]
                                  : m2[(long)b * m2_bs + jj - msplit];
        }
        __syncthreads();
        if (act) {
            for (int j = 0; j < cnt; j++) {
                float sc = 0.f;
                #pragma unroll
                for (int d = 0; d < 32; d++) sc += q[d] * ks[j][d];
                if (mk[j]) sc = -1e9f;
                if (sc > m) {
                    float r = __expf(m - sc);
                    l = l * r + 1.f;
                    #pragma unroll
                    for (int d = 0; d < 32; d++) o[d] = o[d] * r + vs[j][d];
                    m = sc;
                } else {
                    float p = __expf(sc - m);
                    l += p;
                    #pragma unroll
                    for (int d = 0; d < 32; d++) o[d] += p * vs[j][d];
                }
            }
        }
    }
    if (act) {
        float inv = 1.f / l;
        float* Ob = O + ((long)b * Tq + tid) * Dm + h * 32;
        #pragma unroll
        for (int d = 0; d < 32; d++) Ob[d] = o[d] * inv;
    }
}

// ---------------- residual + layernorm ----------------
__global__ void resid_ln(const float* __restrict__ X, const float* __restrict__ Y,
                         const float* __restrict__ Wb, const float* __restrict__ Bb,
                         const int* __restrict__ sid, float* __restrict__ Out)
{
    const int row = blockIdx.x;
    const int b = row / Tq;
    const int i = threadIdx.x;
    const int s = sid[b];
    float v = X[(long)row * Dm + i] + Y[(long)row * Dm + i];

    float sum = v, sq = v * v;
    #pragma unroll
    for (int off = 16; off > 0; off >>= 1) {
        sum += __shfl_xor_sync(0xffffffffu, sum, off);
        sq  += __shfl_xor_sync(0xffffffffu, sq,  off);
    }
    __shared__ float sS[8], sQ[8];
    if ((i & 31) == 0) { sS[i >> 5] = sum; sQ[i >> 5] = sq; }
    __syncthreads();
    float ts = 0.f, tq = 0.f;
    #pragma unroll
    for (int k = 0; k < 8; k++) { ts += sS[k]; tq += sQ[k]; }

    float mean = ts * (1.f / 256.f);
    float var  = tq * (1.f / 256.f) - mean * mean;
    float rstd = rsqrtf(var + 1e-5f);
    Out[(long)row * Dm + i] = (v - mean) * rstd * Wb[(long)s * Dm + i] + Bb[(long)s * Dm + i];
}

// ---------------------------------- launch ---------------------------------------------
extern "C" void kernel_launch(void* const* d_in, const int* in_sizes, int n_in,
                              void* d_out, int out_size)
{
    const float*         text  = (const float*)d_in[0];
    const unsigned char* tmask = (const unsigned char*)d_in[1];
    const float*         im1   = (const float*)d_in[2];
    const unsigned char* imk1  = (const unsigned char*)d_in[3];
    const float*         im2   = (const float*)d_in[4];
    const unsigned char* imk2  = (const unsigned char*)d_in[5];
    const int*           sid   = (const int*)d_in[6];
    const float* sa_in_w  = (const float*)d_in[7];
    const float* sa_in_b  = (const float*)d_in[8];
    const float* sa_out_w = (const float*)d_in[9];
    const float* sa_out_b = (const float*)d_in[10];
    const float* ca_in_w  = (const float*)d_in[11];
    const float* ca_in_b  = (const float*)d_in[12];
    const float* ca_out_w = (const float*)d_in[13];
    const float* ca_out_b = (const float*)d_in[14];
    const float* l1w = (const float*)d_in[15];
    const float* l1b = (const float*)d_in[16];
    const float* l2w = (const float*)d_in[17];
    const float* l2b = (const float*)d_in[18];
    const float* n1w = (const float*)d_in[19];
    const float* n1b = (const float*)d_in[20];
    const float* n2w = (const float*)d_in[21];
    const float* n2b = (const float*)d_in[22];
    const float* n3w = (const float*)d_in[23];
    const float* n3b = (const float*)d_in[24];
    float* out = (float*)d_out;

    static float *qkv=nullptr,*attn=nullptr,*proj=nullptr,*x1=nullptr,*x2=nullptr,
                 *caq=nullptr,*cakv=nullptr,*ffh=nullptr;
    if (!qkv) {
        cudaGetSymbolAddress((void**)&qkv,  g_qkv);
        cudaGetSymbolAddress((void**)&attn, g_attn);
        cudaGetSymbolAddress((void**)&proj, g_proj);
        cudaGetSymbolAddress((void**)&x1,   g_x1);
        cudaGetSymbolAddress((void**)&x2,   g_x2);
        cudaGetSymbolAddress((void**)&caq,  g_caq);
        cudaGetSymbolAddress((void**)&cakv, g_cakv);
        cudaGetSymbolAddress((void**)&ffh,  g_ffh);
        cudaFuncSetAttribute(gemm_mma<false>, cudaFuncAttributeMaxDynamicSharedMemorySize, SMT);
        cudaFuncSetAttribute(gemm_mma<true>,  cudaFuncAttributeMaxDynamicSharedMemorySize, SMT);
    }

    const int LNROWS = Bsz * Tq;

    // 1) SA qkv projection: (77,768) = text @ sa_in_w^T
    gemm_mma<false><<<dim3(768/128, 2, Bsz), 256, SMT>>>(
        text, text, Tq, (long)Tq*Dm,
        sa_in_w, (long)768*Dm, 0, sa_in_b, 768, sid,
        qkv, (long)Tq*768, Tq, 768, Dm);

    // 2) SA attention
    attn_kernel<<<dim3(Hh, Bsz), 128>>>(
        qkv,       768, (long)Tq*768,
        qkv + 256, 768, (long)Tq*768,
        qkv + 512, 768, (long)Tq*768,
        tmask, Tq, tmask, 0, Tq + 1,
        Tq, attn);

    // 3) SA out proj
    gemm_mma<false><<<dim3(Dm/128, 2, Bsz), 256, SMT>>>(
        attn, attn, Tq, (long)Tq*Dm,
        sa_out_w, (long)Dm*Dm, 0, sa_out_b, Dm, sid,
        proj, (long)Tq*Dm, Tq, Dm, Dm);

    // 4) residual + LN1 -> x1
    resid_ln<<<LNROWS, 256>>>(text, proj, n1w, n1b, sid, x1);

    // 5) CA query proj (rows [0:256) of ca_in_w)
    gemm_mma<false><<<dim3(Dm/128, 2, Bsz), 256, SMT>>>(
        x1, x1, Tq, (long)Tq*Dm,
        ca_in_w, (long)768*Dm, 0, ca_in_b, 768, sid,
        caq, (long)Tq*Dm, Tq, Dm, Dm);

    // 6) CA key/value proj from concat(im1,im2), rows [256:768) of ca_in_w
    gemm_mma<false><<<dim3(512/128, (Mem+63)/64, Bsz), 256, SMT>>>(
        im1, im2, 400, (long)400*Dm,
        ca_in_w, (long)768*Dm, 256, ca_in_b, 768, sid,
        cakv, (long)Mem*512, Mem, 512, Dm);

    // 7) CA attention (nk=800, split masks at 400)
    attn_kernel<<<dim3(Hh, Bsz), 128>>>(
        caq,        Dm,  (long)Tq*Dm,
        cakv,       512, (long)Mem*512,
        cakv + 256, 512, (long)Mem*512,
        imk1, 400, imk2, 400, 400,
        Mem, attn);

    // 8) CA out proj
    gemm_mma<false><<<dim3(Dm/128, 2, Bsz), 256, SMT>>>(
        attn, attn, Tq, (long)Tq*Dm,
        ca_out_w, (long)Dm*Dm, 0, ca_out_b, Dm, sid,
        proj, (long)Tq*Dm, Tq, Dm, Dm);

    // 9) residual + LN2 -> x2
    resid_ln<<<LNROWS, 256>>>(x1, proj, n2w, n2b, sid, x2);

    // 10) FFN up + relu
    gemm_mma<true><<<dim3(DFFm/128, 2, Bsz), 256, SMT>>>(
        x2, x2, Tq, (long)Tq*Dm,
        l1w, (long)DFFm*Dm, 0, l1b, DFFm, sid,
        ffh, (long)Tq*DFFm, Tq, DFFm, Dm);

    // 11) FFN down
    gemm_mma<false><<<dim3(Dm/128, 2, Bsz), 256, SMT>>>(
        ffh, ffh, Tq, (long)Tq*DFFm,
        l2w, (long)Dm*DFFm, 0, l2b, Dm, sid,
        proj, (long)Tq*Dm, Tq, Dm, DFFm);

    // 12) residual + LN3 -> output
    resid_ln<<<LNROWS, 256>>>(x2, proj, n3w, n3b, sid, out);
}